// round 9
// baseline (speedup 1.0000x reference)
#include <cuda_runtime.h>
#include <cuda_bf16.h>
#include <math_constants.h>

#define N_NODES 50000
#define N_EDGES 800000
#define DOUT 128

// scratch (device globals — no allocation allowed)
__device__ float g_h[(size_t)N_NODES * DOUT];   // 25.6 MB
__device__ float g_sdst[N_NODES];
__device__ float g_ssrc[N_NODES];
__device__ int   g_rowptr[N_NODES + 1];

// ---------------------------------------------------------------------------
// helpers
// ---------------------------------------------------------------------------
__device__ __forceinline__ unsigned long long pk2(float lo, float hi) {
    unsigned long long r;
    asm("mov.b64 %0, {%1, %2};" : "=l"(r) : "f"(lo), "f"(hi));
    return r;
}
__device__ __forceinline__ void upk2(unsigned long long v, float& lo, float& hi) {
    asm("mov.b64 {%0, %1}, %2;" : "=f"(lo), "=f"(hi) : "l"(v));
}
__device__ __forceinline__ void ffma2(unsigned long long& d,
                                      unsigned long long a, unsigned long long b) {
    asm("fma.rn.f32x2 %0, %1, %2, %0;" : "+l"(d) : "l"(a), "l"(b));
}
__device__ __forceinline__ unsigned f2tf32(float f) {
    unsigned r;
    asm("cvt.rna.tf32.f32 %0, %1;" : "=r"(r) : "f"(f));
    return r;
}
__device__ __forceinline__ void mma_tf32(float* c,
    unsigned a0, unsigned a1, unsigned a2, unsigned a3,
    unsigned b0, unsigned b1)
{
    asm volatile(
        "mma.sync.aligned.m16n8k8.row.col.f32.tf32.tf32.f32 "
        "{%0,%1,%2,%3}, {%4,%5,%6,%7}, {%8,%9}, {%0,%1,%2,%3};\n"
        : "+f"(c[0]), "+f"(c[1]), "+f"(c[2]), "+f"(c[3])
        : "r"(a0), "r"(a1), "r"(a2), "r"(a3), "r"(b0), "r"(b1));
}

// ---------------------------------------------------------------------------
// K1: h = x @ W + b  AND  s_dst/s_src scores, fused. 3xTF32 tensor-core GEMM.
//     128x128 block tile, BK=16, 8 warps (4M x 2N), warp tile 32x64.
//     smem k-permuted layout: pos(k) = (k%4)*4 + k/4 so each mma fragment
//     load is one LDS.128; X side XOR-swizzled by row&3 to cut STS conflicts.
// ---------------------------------------------------------------------------
__global__ __launch_bounds__(256) void gemm_score_kernel(
    const float* __restrict__ x, const float* __restrict__ W,
    const float* __restrict__ b, const float* __restrict__ a_w,
    float* __restrict__ h, int N)
{
    __shared__ unsigned Xhi[128][16], Xlo[128][16];   // [row][kpos]
    __shared__ unsigned Whi[128][16], Wlo[128][16];   // [n][kpos]
    __shared__ float sPartD[2][128], sPartS[2][128];

    const int tid  = threadIdx.x;
    const int wid  = tid >> 5;
    const int lane = tid & 31;
    const int g    = lane >> 2;    // group id (rows / n)
    const int tig  = lane & 3;     // thread in group (k)
    const int rowBase = blockIdx.x * 128;

    const int warpM = (wid >> 1) * 32;
    const int warpN = (wid & 1) * 64;

    float c[2][8][4];
    #pragma unroll
    for (int mf = 0; mf < 2; ++mf)
        #pragma unroll
        for (int nf = 0; nf < 8; ++nf)
            #pragma unroll
            for (int r = 0; r < 4; ++r) c[mf][nf][r] = 0.f;

    // tile-load thread maps
    const int lx_row = tid >> 1;          // 0..127
    const int lx_kb  = (tid & 1) * 8;     // 0 or 8
    const int lw_k   = tid & 15;          // 0..15
    const int lw_nb  = (tid >> 4) * 8;    // 0..120

    // A-frag smem column base (XOR swizzle; row&3 == g&3 for all 4 row reads)
    const int axc = 4 * (tig ^ (g & 3));

    for (int kt = 0; kt < 128; kt += 16) {
        // ---- fetch gmem ----
        float4 xv0 = make_float4(0.f, 0.f, 0.f, 0.f), xv1 = xv0;
        {
            int grow = rowBase + lx_row;
            if (grow < N) {
                const float* xp = x + (size_t)grow * 128 + kt + lx_kb;
                xv0 = *(const float4*)xp;
                xv1 = *(const float4*)(xp + 4);
            }
        }
        float4 wv0, wv1;
        {
            const float* wp = W + (size_t)(kt + lw_k) * 128 + lw_nb;
            wv0 = *(const float4*)wp;
            wv1 = *(const float4*)(wp + 4);
        }

        __syncthreads();   // previous tile fully consumed

        // ---- convert + store X (pos ^ ((row&3)<<2)) ----
        {
            const int sw = (lx_row & 3) << 2;
            float vals[8] = {xv0.x, xv0.y, xv0.z, xv0.w, xv1.x, xv1.y, xv1.z, xv1.w};
            #pragma unroll
            for (int cc = 0; cc < 8; ++cc) {
                int kl  = lx_kb + cc;
                int pos = ((kl & 3) * 4 + (kl >> 2)) ^ sw;
                unsigned hi = f2tf32(vals[cc]);
                Xhi[lx_row][pos] = hi;
                Xlo[lx_row][pos] = f2tf32(vals[cc] - __uint_as_float(hi));
            }
        }
        // ---- convert + store W (no swizzle) ----
        {
            const int pos = (lw_k & 3) * 4 + (lw_k >> 2);
            float vals[8] = {wv0.x, wv0.y, wv0.z, wv0.w, wv1.x, wv1.y, wv1.z, wv1.w};
            #pragma unroll
            for (int cc = 0; cc < 8; ++cc) {
                unsigned hi = f2tf32(vals[cc]);
                Whi[lw_nb + cc][pos] = hi;
                Wlo[lw_nb + cc][pos] = f2tf32(vals[cc] - __uint_as_float(hi));
            }
        }
        __syncthreads();

        // ---- A fragments: rows g, g+8, g+16, g+24 (both k8 steps in one uint4)
        uint4 Ah[4], Al[4];
        #pragma unroll
        for (int rr = 0; rr < 4; ++rr) {
            int row = warpM + g + rr * 8;
            Ah[rr] = *(const uint4*)&Xhi[row][axc];
            Al[rr] = *(const uint4*)&Xlo[row][axc];
        }

        // ---- mma over 8 n-frags ----
        #pragma unroll
        for (int nf = 0; nf < 8; ++nf) {
            int n = warpN + nf * 8 + g;
            uint4 bh = *(const uint4*)&Whi[n][tig * 4];
            uint4 bl = *(const uint4*)&Wlo[n][tig * 4];
            #pragma unroll
            for (int mf = 0; mf < 2; ++mf) {
                uint4 ah0 = Ah[mf * 2];      // rows base
                uint4 ah1 = Ah[mf * 2 + 1];  // rows base+8
                uint4 al0 = Al[mf * 2];
                uint4 al1 = Al[mf * 2 + 1];
                // k8 step 0
                mma_tf32(c[mf][nf], ah0.x, ah1.x, ah0.y, ah1.y, bh.x, bh.y);
                mma_tf32(c[mf][nf], ah0.x, ah1.x, ah0.y, ah1.y, bl.x, bl.y);
                mma_tf32(c[mf][nf], al0.x, al1.x, al0.y, al1.y, bh.x, bh.y);
                // k8 step 1
                mma_tf32(c[mf][nf], ah0.z, ah1.z, ah0.w, ah1.w, bh.z, bh.w);
                mma_tf32(c[mf][nf], ah0.z, ah1.z, ah0.w, ah1.w, bl.z, bl.w);
                mma_tf32(c[mf][nf], al0.z, al1.z, al0.w, al1.w, bh.z, bh.w);
            }
        }
    }

    // ---- epilogue: bias, store h, fused scores ----
    #pragma unroll
    for (int mf = 0; mf < 2; ++mf) {
        #pragma unroll
        for (int half = 0; half < 2; ++half) {
            int lrow = warpM + mf * 16 + half * 8 + g;
            int grow = rowBase + lrow;
            float sd = 0.f, ss = 0.f;
            #pragma unroll
            for (int nf = 0; nf < 8; ++nf) {
                int col = warpN + nf * 8 + tig * 2;
                float o0 = c[mf][nf][half * 2 + 0] + __ldg(b + col);
                float o1 = c[mf][nf][half * 2 + 1] + __ldg(b + col + 1);
                if (grow < N)
                    *(float2*)(h + (size_t)grow * 128 + col) = make_float2(o0, o1);
                sd += o0 * __ldg(a_w + col)       + o1 * __ldg(a_w + col + 1);
                ss += o0 * __ldg(a_w + 128 + col) + o1 * __ldg(a_w + 129 + col);
            }
            // reduce over the 4 lanes (tig) sharing this row
            #pragma unroll
            for (int o = 1; o <= 2; o <<= 1) {
                sd += __shfl_xor_sync(0xFFFFFFFFu, sd, o);
                ss += __shfl_xor_sync(0xFFFFFFFFu, ss, o);
            }
            if (tig == 0) {
                sPartD[wid & 1][lrow] = sd;
                sPartS[wid & 1][lrow] = ss;
            }
        }
    }
    __syncthreads();
    if (tid < 128) {
        int grow = rowBase + tid;
        if (grow < N) {
            g_sdst[grow] = sPartD[0][tid] + sPartD[1][tid];
            g_ssrc[grow] = sPartS[0][tid] + sPartS[1][tid];
        }
    }
}

// ---------------------------------------------------------------------------
// K2: row_ptr via lower_bound on sorted edge_dst
// ---------------------------------------------------------------------------
__global__ __launch_bounds__(256) void rowptr_kernel(const int* __restrict__ edge_dst,
                                                     int N, int E)
{
    int n = blockIdx.x * blockDim.x + threadIdx.x;
    if (n > N) return;
    int lo = 0, hi = E;
    while (lo < hi) {
        int mid = (lo + hi) >> 1;
        if (edge_dst[mid] < n) lo = mid + 1; else hi = mid;
    }
    g_rowptr[n] = lo;
}

// ---------------------------------------------------------------------------
// K3: warp-per-dst-node SINGLE-PASS segment softmax + aggregation.
//     (shift-invariant softmax, logits O(±10): exp taken directly)
// ---------------------------------------------------------------------------
__global__ __launch_bounds__(256) void agg_kernel(const int* __restrict__ edge_src,
                                                  const float* __restrict__ a_b,
                                                  float* __restrict__ out, int N)
{
    int warp = (blockIdx.x * blockDim.x + threadIdx.x) >> 5;
    int lane = threadIdx.x & 31;
    if (warp >= N) return;

    int s = g_rowptr[warp];
    int e = g_rowptr[warp + 1];
    float4* op = (float4*)(out + (size_t)warp * 128);

    if (s == e) { op[lane] = make_float4(0.f, 0.f, 0.f, 0.f); return; }

    float base = g_sdst[warp] + a_b[0];

    float sum = 0.f;
    unsigned long long accA01 = 0ull, accA23 = 0ull;
    unsigned long long accB01 = 0ull, accB23 = 0ull;

    for (int chunk = s; chunk < e; chunk += 32) {
        int i = chunk + lane;
        int src = 0;
        float w = 0.f;
        if (i < e) {
            src = edge_src[i];
            float l = base + g_ssrc[src];
            l = (l >= 0.f) ? l : 0.01f * l;
            w = __expf(l);
        }
        sum += w;
        int cnt = min(32, e - chunk);
        int j = 0;
        #pragma unroll 2
        for (; j + 2 <= cnt; j += 2) {
            float wj0 = __shfl_sync(0xFFFFFFFFu, w, j);
            int   sj0 = __shfl_sync(0xFFFFFFFFu, src, j);
            float wj1 = __shfl_sync(0xFFFFFFFFu, w, j + 1);
            int   sj1 = __shfl_sync(0xFFFFFFFFu, src, j + 1);
            float4 v0 = ((const float4*)(g_h + (size_t)sj0 * 128))[lane];
            float4 v1 = ((const float4*)(g_h + (size_t)sj1 * 128))[lane];
            unsigned long long w20 = pk2(wj0, wj0);
            unsigned long long w21 = pk2(wj1, wj1);
            ffma2(accA01, w20, pk2(v0.x, v0.y));
            ffma2(accA23, w20, pk2(v0.z, v0.w));
            ffma2(accB01, w21, pk2(v1.x, v1.y));
            ffma2(accB23, w21, pk2(v1.z, v1.w));
        }
        if (j < cnt) {
            float wj = __shfl_sync(0xFFFFFFFFu, w, j);
            int   sj = __shfl_sync(0xFFFFFFFFu, src, j);
            float4 v = ((const float4*)(g_h + (size_t)sj * 128))[lane];
            unsigned long long w2 = pk2(wj, wj);
            ffma2(accA01, w2, pk2(v.x, v.y));
            ffma2(accA23, w2, pk2(v.z, v.w));
        }
    }
    #pragma unroll
    for (int o = 16; o; o >>= 1)
        sum += __shfl_xor_sync(0xFFFFFFFFu, sum, o);

    float inv = 1.0f / fmaxf(sum, 1e-16f);

    float a0, a1, a2, a3, b0, b1, b2, b3;
    upk2(accA01, a0, a1); upk2(accA23, a2, a3);
    upk2(accB01, b0, b1); upk2(accB23, b2, b3);
    op[lane] = make_float4((a0 + b0) * inv, (a1 + b1) * inv,
                           (a2 + b2) * inv, (a3 + b3) * inv);
}

// ---------------------------------------------------------------------------
extern "C" void kernel_launch(void* const* d_in, const int* in_sizes, int n_in,
                              void* d_out, int out_size)
{
    const float* x        = (const float*)d_in[0];
    const int*   edge_src = (const int*)d_in[1];
    const int*   edge_dst = (const int*)d_in[2];
    const float* W        = (const float*)d_in[3];
    const float* b        = (const float*)d_in[4];
    const float* a_w      = (const float*)d_in[5];
    const float* a_b      = (const float*)d_in[6];
    float*       out      = (float*)d_out;

    const int N = in_sizes[0] / DOUT;   // 50000
    const int E = in_sizes[1];          // 800000

    float* h_ptr;
    cudaGetSymbolAddress((void**)&h_ptr, g_h);

    gemm_score_kernel<<<(N + 127) / 128, 256>>>(x, W, b, a_w, h_ptr, N);
    rowptr_kernel<<<(N + 1 + 255) / 256, 256>>>(edge_dst, N, E);
    agg_kernel<<<(N + 7) / 8, 256>>>(edge_src, a_b, out, N);
}

// round 10
// speedup vs baseline: 1.2313x; 1.2313x over previous
#include <cuda_runtime.h>
#include <cuda_bf16.h>
#include <math_constants.h>

#define N_NODES 50000
#define N_EDGES 800000
#define DOUT 128

// scratch (device globals — no allocation allowed)
__device__ float g_h[(size_t)N_NODES * DOUT];   // 25.6 MB
__device__ float g_sdst[N_NODES];
__device__ float g_ssrc[N_NODES];
__device__ int   g_rowptr[N_NODES + 1];

// ---------------------------------------------------------------------------
// helpers
// ---------------------------------------------------------------------------
__device__ __forceinline__ unsigned long long pk2(float lo, float hi) {
    unsigned long long r;
    asm("mov.b64 %0, {%1, %2};" : "=l"(r) : "f"(lo), "f"(hi));
    return r;
}
__device__ __forceinline__ void upk2(unsigned long long v, float& lo, float& hi) {
    asm("mov.b64 {%0, %1}, %2;" : "=f"(lo), "=f"(hi) : "l"(v));
}
__device__ __forceinline__ void ffma2(unsigned long long& d,
                                      unsigned long long a, unsigned long long b) {
    asm("fma.rn.f32x2 %0, %1, %2, %0;" : "+l"(d) : "l"(a), "l"(b));
}
__device__ __forceinline__ unsigned sptr(const void* p) {
    return (unsigned)__cvta_generic_to_shared(p);
}
// pack two floats to bf16x2 (lo half = a, hi half = b)
__device__ __forceinline__ unsigned pack_bf2(float a, float b) {
    __nv_bfloat162 t = __floats2bfloat162_rn(a, b);
    return *(unsigned*)&t;
}
__device__ __forceinline__ void ldsm_x4(unsigned addr, unsigned& r0, unsigned& r1,
                                        unsigned& r2, unsigned& r3) {
    asm volatile("ldmatrix.sync.aligned.m8n8.x4.shared.b16 {%0,%1,%2,%3}, [%4];"
                 : "=r"(r0), "=r"(r1), "=r"(r2), "=r"(r3) : "r"(addr));
}
__device__ __forceinline__ void ldsm_x2t(unsigned addr, unsigned& r0, unsigned& r1) {
    asm volatile("ldmatrix.sync.aligned.m8n8.x2.trans.shared.b16 {%0,%1}, [%2];"
                 : "=r"(r0), "=r"(r1) : "r"(addr));
}
__device__ __forceinline__ void mma_bf16(float* c, unsigned a0, unsigned a1,
                                         unsigned a2, unsigned a3,
                                         unsigned b0, unsigned b1) {
    asm volatile(
        "mma.sync.aligned.m16n8k16.row.col.f32.bf16.bf16.f32 "
        "{%0,%1,%2,%3}, {%4,%5,%6,%7}, {%8,%9}, {%0,%1,%2,%3};\n"
        : "+f"(c[0]), "+f"(c[1]), "+f"(c[2]), "+f"(c[3])
        : "r"(a0), "r"(a1), "r"(a2), "r"(a3), "r"(b0), "r"(b1));
}

// ---------------------------------------------------------------------------
// K1: h = x @ W + b  AND  s_dst/s_src, fused. bf16x2 (3-term) tensor GEMM.
//     128x128 block tile, BK=32 (4 tiles), 8 warps (4M x 2N), warp 32x64.
//     W converted to bf16 hi/lo in smem once per block; X streamed.
//     ldmatrix for all fragments; padded rows -> conflict-free.
// ---------------------------------------------------------------------------
#define WROW 136   // bf16 per W smem row (128 + 8 pad)
#define XROW 40    // bf16 per X smem row (32 + 8 pad)

__global__ __launch_bounds__(256) void gemm_score_kernel(
    const float* __restrict__ x, const float* __restrict__ W,
    const float* __restrict__ b, const float* __restrict__ a_w,
    float* __restrict__ h, int N)
{
    extern __shared__ char smem[];
    __nv_bfloat16* Whi = (__nv_bfloat16*)smem;                       // [128][WROW]
    __nv_bfloat16* Wlo = (__nv_bfloat16*)(smem + 34816);
    __nv_bfloat16* Xhi = (__nv_bfloat16*)(smem + 69632);             // [128][XROW]
    __nv_bfloat16* Xlo = (__nv_bfloat16*)(smem + 79872);
    float* sPartD = (float*)(smem + 90112);                          // [2][128]
    float* sPartS = (float*)(smem + 91136);                          // [2][128]

    const int tid  = threadIdx.x;
    const int wid  = tid >> 5;
    const int lane = tid & 31;
    const int rowBase = blockIdx.x * 128;

    const int warpM = (wid >> 1) * 32;
    const int warpN = (wid & 1) * 64;

    // ---- one-time: convert W (fp32 [k][n]) -> smem bf16 hi/lo [k][n] ----
    #pragma unroll
    for (int it = 0; it < 8; ++it) {
        int idx8 = tid + it * 256;          // 0..2047
        int k   = idx8 >> 4;
        int n8  = (idx8 & 15) * 8;
        const float4* wp = (const float4*)(W + (size_t)k * 128 + n8);
        float4 f0 = wp[0], f1 = wp[1];
        float vf[8] = {f0.x, f0.y, f0.z, f0.w, f1.x, f1.y, f1.z, f1.w};
        unsigned hiw[4], low[4];
        #pragma unroll
        for (int p = 0; p < 4; ++p) {
            float va = vf[p * 2], vb = vf[p * 2 + 1];
            __nv_bfloat16 ha = __float2bfloat16_rn(va);
            __nv_bfloat16 hb = __float2bfloat16_rn(vb);
            float ra = va - __bfloat162float(ha);
            float rb = vb - __bfloat162float(hb);
            hiw[p] = pack_bf2(__bfloat162float(ha), __bfloat162float(hb));
            low[p] = pack_bf2(ra, rb);
        }
        *(uint4*)(Whi + (size_t)k * WROW + n8) = *(uint4*)hiw;
        *(uint4*)(Wlo + (size_t)k * WROW + n8) = *(uint4*)low;
    }

    float c[2][8][4];
    #pragma unroll
    for (int mf = 0; mf < 2; ++mf)
        #pragma unroll
        for (int nf = 0; nf < 8; ++nf)
            #pragma unroll
            for (int r = 0; r < 4; ++r) c[mf][nf][r] = 0.f;

    // X fetch map: row = tid>>1, 16 k per thread
    const int lx_row = tid >> 1;
    const int lx_kb  = (tid & 1) * 16;
    const int grow_l = rowBase + lx_row;

    // fragment addresses (constant across tiles)
    const unsigned a_off = (unsigned)((warpM + (lane & 15)) * XROW + (lane >> 4) * 8);
    unsigned aHi_base = sptr(Xhi) + a_off * 2;
    unsigned aLo_base = sptr(Xlo) + a_off * 2;

    float4 fx[4];
    {   // prefetch tile 0
        const float* xp = x + (size_t)grow_l * 128 + lx_kb;
        if (grow_l < N) {
            fx[0] = *(const float4*)(xp);      fx[1] = *(const float4*)(xp + 4);
            fx[2] = *(const float4*)(xp + 8);  fx[3] = *(const float4*)(xp + 12);
        } else {
            fx[0] = fx[1] = fx[2] = fx[3] = make_float4(0.f, 0.f, 0.f, 0.f);
        }
    }

    for (int t = 0; t < 4; ++t) {
        __syncthreads();   // smem (X) free / W ready on t==0
        // cvt + store X tile
        {
            float vf[16] = {fx[0].x, fx[0].y, fx[0].z, fx[0].w,
                            fx[1].x, fx[1].y, fx[1].z, fx[1].w,
                            fx[2].x, fx[2].y, fx[2].z, fx[2].w,
                            fx[3].x, fx[3].y, fx[3].z, fx[3].w};
            __nv_bfloat16* xh = Xhi + (size_t)lx_row * XROW + lx_kb;
            __nv_bfloat16* xl = Xlo + (size_t)lx_row * XROW + lx_kb;
            #pragma unroll
            for (int p = 0; p < 8; ++p) {
                float va = vf[p * 2], vb = vf[p * 2 + 1];
                __nv_bfloat16 ha = __float2bfloat16_rn(va);
                __nv_bfloat16 hb = __float2bfloat16_rn(vb);
                float ra = va - __bfloat162float(ha);
                float rb = vb - __bfloat162float(hb);
                *(unsigned*)(xh + p * 2) = pack_bf2(__bfloat162float(ha), __bfloat162float(hb));
                *(unsigned*)(xl + p * 2) = pack_bf2(ra, rb);
            }
        }
        __syncthreads();

        if (t < 3) {   // prefetch next tile (hidden under HMMA)
            const float* xp = x + (size_t)grow_l * 128 + (t + 1) * 32 + lx_kb;
            if (grow_l < N) {
                fx[0] = *(const float4*)(xp);      fx[1] = *(const float4*)(xp + 4);
                fx[2] = *(const float4*)(xp + 8);  fx[3] = *(const float4*)(xp + 12);
            }
        }

        // compute: 2 k16 steps in this tile
        #pragma unroll
        for (int kk = 0; kk < 32; kk += 16) {
            unsigned Ah[2][4], Al[2][4];
            #pragma unroll
            for (int mf = 0; mf < 2; ++mf) {
                unsigned off = (unsigned)(mf * 16 * XROW + kk) * 2;
                ldsm_x4(aHi_base + off, Ah[mf][0], Ah[mf][1], Ah[mf][2], Ah[mf][3]);
                ldsm_x4(aLo_base + off, Al[mf][0], Al[mf][1], Al[mf][2], Al[mf][3]);
            }
            int kabs = t * 32 + kk;
            #pragma unroll
            for (int nf = 0; nf < 8; ++nf) {
                int n = warpN + nf * 8;
                unsigned boff = (unsigned)((kabs + (lane & 15)) * WROW + n) * 2;
                unsigned bh0, bh1, bl0, bl1;
                ldsm_x2t(sptr(Whi) + boff, bh0, bh1);
                ldsm_x2t(sptr(Wlo) + boff, bl0, bl1);
                #pragma unroll
                for (int mf = 0; mf < 2; ++mf) {
                    mma_bf16(c[mf][nf], Ah[mf][0], Ah[mf][1], Ah[mf][2], Ah[mf][3], bh0, bh1);
                    mma_bf16(c[mf][nf], Ah[mf][0], Ah[mf][1], Ah[mf][2], Ah[mf][3], bl0, bl1);
                    mma_bf16(c[mf][nf], Al[mf][0], Al[mf][1], Al[mf][2], Al[mf][3], bh0, bh1);
                }
            }
        }
    }

    // ---- epilogue: bias, store h, fused scores ----
    const int g   = lane >> 2;
    const int tig = lane & 3;
    #pragma unroll
    for (int mf = 0; mf < 2; ++mf) {
        #pragma unroll
        for (int half = 0; half < 2; ++half) {
            int lrow = warpM + mf * 16 + half * 8 + g;
            int grow = rowBase + lrow;
            float sd = 0.f, ss = 0.f;
            #pragma unroll
            for (int nf = 0; nf < 8; ++nf) {
                int col = warpN + nf * 8 + tig * 2;
                float o0 = c[mf][nf][half * 2 + 0] + __ldg(b + col);
                float o1 = c[mf][nf][half * 2 + 1] + __ldg(b + col + 1);
                if (grow < N)
                    *(float2*)(h + (size_t)grow * 128 + col) = make_float2(o0, o1);
                sd += o0 * __ldg(a_w + col)       + o1 * __ldg(a_w + col + 1);
                ss += o0 * __ldg(a_w + 128 + col) + o1 * __ldg(a_w + 129 + col);
            }
            #pragma unroll
            for (int o = 1; o <= 2; o <<= 1) {
                sd += __shfl_xor_sync(0xFFFFFFFFu, sd, o);
                ss += __shfl_xor_sync(0xFFFFFFFFu, ss, o);
            }
            if (tig == 0) {
                sPartD[(wid & 1) * 128 + lrow] = sd;
                sPartS[(wid & 1) * 128 + lrow] = ss;
            }
        }
    }
    __syncthreads();
    if (tid < 128) {
        int grow = rowBase + tid;
        if (grow < N) {
            g_sdst[grow] = sPartD[tid] + sPartD[128 + tid];
            g_ssrc[grow] = sPartS[tid] + sPartS[128 + tid];
        }
    }
}

// ---------------------------------------------------------------------------
// K2: row_ptr via lower_bound on sorted edge_dst
// ---------------------------------------------------------------------------
__global__ __launch_bounds__(256) void rowptr_kernel(const int* __restrict__ edge_dst,
                                                     int N, int E)
{
    int n = blockIdx.x * blockDim.x + threadIdx.x;
    if (n > N) return;
    int lo = 0, hi = E;
    while (lo < hi) {
        int mid = (lo + hi) >> 1;
        if (edge_dst[mid] < n) lo = mid + 1; else hi = mid;
    }
    g_rowptr[n] = lo;
}

// ---------------------------------------------------------------------------
// K3: warp-per-dst-node SINGLE-PASS segment softmax + aggregation.
//     (shift-invariant softmax, logits O(±10): exp taken directly)
// ---------------------------------------------------------------------------
__global__ __launch_bounds__(256) void agg_kernel(const int* __restrict__ edge_src,
                                                  const float* __restrict__ a_b,
                                                  float* __restrict__ out, int N)
{
    int warp = (blockIdx.x * blockDim.x + threadIdx.x) >> 5;
    int lane = threadIdx.x & 31;
    if (warp >= N) return;

    int s = g_rowptr[warp];
    int e = g_rowptr[warp + 1];
    float4* op = (float4*)(out + (size_t)warp * 128);

    if (s == e) { op[lane] = make_float4(0.f, 0.f, 0.f, 0.f); return; }

    float base = g_sdst[warp] + a_b[0];

    float sum = 0.f;
    unsigned long long accA01 = 0ull, accA23 = 0ull;
    unsigned long long accB01 = 0ull, accB23 = 0ull;

    for (int chunk = s; chunk < e; chunk += 32) {
        int i = chunk + lane;
        int src = 0;
        float w = 0.f;
        if (i < e) {
            src = edge_src[i];
            float l = base + g_ssrc[src];
            l = (l >= 0.f) ? l : 0.01f * l;
            w = __expf(l);
        }
        sum += w;
        int cnt = min(32, e - chunk);
        int j = 0;
        #pragma unroll 2
        for (; j + 2 <= cnt; j += 2) {
            float wj0 = __shfl_sync(0xFFFFFFFFu, w, j);
            int   sj0 = __shfl_sync(0xFFFFFFFFu, src, j);
            float wj1 = __shfl_sync(0xFFFFFFFFu, w, j + 1);
            int   sj1 = __shfl_sync(0xFFFFFFFFu, src, j + 1);
            float4 v0 = ((const float4*)(g_h + (size_t)sj0 * 128))[lane];
            float4 v1 = ((const float4*)(g_h + (size_t)sj1 * 128))[lane];
            unsigned long long w20 = pk2(wj0, wj0);
            unsigned long long w21 = pk2(wj1, wj1);
            ffma2(accA01, w20, pk2(v0.x, v0.y));
            ffma2(accA23, w20, pk2(v0.z, v0.w));
            ffma2(accB01, w21, pk2(v1.x, v1.y));
            ffma2(accB23, w21, pk2(v1.z, v1.w));
        }
        if (j < cnt) {
            float wj = __shfl_sync(0xFFFFFFFFu, w, j);
            int   sj = __shfl_sync(0xFFFFFFFFu, src, j);
            float4 v = ((const float4*)(g_h + (size_t)sj * 128))[lane];
            unsigned long long w2 = pk2(wj, wj);
            ffma2(accA01, w2, pk2(v.x, v.y));
            ffma2(accA23, w2, pk2(v.z, v.w));
        }
    }
    #pragma unroll
    for (int o = 16; o; o >>= 1)
        sum += __shfl_xor_sync(0xFFFFFFFFu, sum, o);

    float inv = 1.0f / fmaxf(sum, 1e-16f);

    float a0, a1, a2, a3, b0, b1, b2, b3;
    upk2(accA01, a0, a1); upk2(accA23, a2, a3);
    upk2(accB01, b0, b1); upk2(accB23, b2, b3);
    op[lane] = make_float4((a0 + b0) * inv, (a1 + b1) * inv,
                           (a2 + b2) * inv, (a3 + b3) * inv);
}

// ---------------------------------------------------------------------------
extern "C" void kernel_launch(void* const* d_in, const int* in_sizes, int n_in,
                              void* d_out, int out_size)
{
    const float* x        = (const float*)d_in[0];
    const int*   edge_src = (const int*)d_in[1];
    const int*   edge_dst = (const int*)d_in[2];
    const float* W        = (const float*)d_in[3];
    const float* b        = (const float*)d_in[4];
    const float* a_w      = (const float*)d_in[5];
    const float* a_b      = (const float*)d_in[6];
    float*       out      = (float*)d_out;

    const int N = in_sizes[0] / DOUT;   // 50000
    const int E = in_sizes[1];          // 800000

    float* h_ptr;
    cudaGetSymbolAddress((void**)&h_ptr, g_h);

    const int SMEM_BYTES = 92160;
    cudaFuncSetAttribute(gemm_score_kernel,
                         cudaFuncAttributeMaxDynamicSharedMemorySize, SMEM_BYTES);

    gemm_score_kernel<<<(N + 127) / 128, 256, SMEM_BYTES>>>(x, W, b, a_w, h_ptr, N);
    rowptr_kernel<<<(N + 1 + 255) / 256, 256>>>(edge_dst, N, E);
    agg_kernel<<<(N + 7) / 8, 256>>>(edge_src, a_b, out, N);
}

// round 12
// speedup vs baseline: 1.4217x; 1.1547x over previous
#include <cuda_runtime.h>
#include <cuda_bf16.h>
#include <cuda_fp16.h>
#include <math_constants.h>

#define N_NODES 50000
#define N_EDGES 800000
#define DOUT 128

// scratch (device globals — no allocation allowed)
__device__ __half g_h16[(size_t)N_NODES * DOUT];   // 12.8 MB (L2-resident)
__device__ float g_sdst[N_NODES];
__device__ float g_ssrc[N_NODES];
__device__ int   g_rowptr[N_NODES + 1];

// ---------------------------------------------------------------------------
// helpers
// ---------------------------------------------------------------------------
__device__ __forceinline__ unsigned long long pk2(float lo, float hi) {
    unsigned long long r;
    asm("mov.b64 %0, {%1, %2};" : "=l"(r) : "f"(lo), "f"(hi));
    return r;
}
__device__ __forceinline__ void upk2(unsigned long long v, float& lo, float& hi) {
    asm("mov.b64 {%0, %1}, %2;" : "=f"(lo), "=f"(hi) : "l"(v));
}
__device__ __forceinline__ void ffma2(unsigned long long& d,
                                      unsigned long long a, unsigned long long b) {
    asm("fma.rn.f32x2 %0, %1, %2, %0;" : "+l"(d) : "l"(a), "l"(b));
}
__device__ __forceinline__ unsigned sptr(const void* p) {
    return (unsigned)__cvta_generic_to_shared(p);
}
__device__ __forceinline__ unsigned pack_bf2(float a, float b) {
    __nv_bfloat162 t = __floats2bfloat162_rn(a, b);
    return *(unsigned*)&t;
}
__device__ __forceinline__ void ldsm_x4(unsigned addr, unsigned& r0, unsigned& r1,
                                        unsigned& r2, unsigned& r3) {
    asm volatile("ldmatrix.sync.aligned.m8n8.x4.shared.b16 {%0,%1,%2,%3}, [%4];"
                 : "=r"(r0), "=r"(r1), "=r"(r2), "=r"(r3) : "r"(addr));
}
__device__ __forceinline__ void ldsm_x2t(unsigned addr, unsigned& r0, unsigned& r1) {
    asm volatile("ldmatrix.sync.aligned.m8n8.x2.trans.shared.b16 {%0,%1}, [%2];"
                 : "=r"(r0), "=r"(r1) : "r"(addr));
}
__device__ __forceinline__ void mma_bf16(float* c, unsigned a0, unsigned a1,
                                         unsigned a2, unsigned a3,
                                         unsigned b0, unsigned b1) {
    asm volatile(
        "mma.sync.aligned.m16n8k16.row.col.f32.bf16.bf16.f32 "
        "{%0,%1,%2,%3}, {%4,%5,%6,%7}, {%8,%9}, {%0,%1,%2,%3};\n"
        : "+f"(c[0]), "+f"(c[1]), "+f"(c[2]), "+f"(c[3])
        : "r"(a0), "r"(a1), "r"(a2), "r"(a3), "r"(b0), "r"(b1));
}

// ---------------------------------------------------------------------------
// K1: PERSISTENT fused GEMM + scores. bf16x2 (3-term) tensor-core GEMM.
//     grid = #SMs; each block converts W once, then loops over 128-row tiles.
//     Epilogue stores h as fp16 (g_h16) only, plus fused s_dst/s_src.
// ---------------------------------------------------------------------------
#define WROW 136   // bf16 per W smem row (128 + 8 pad)
#define XROW 40    // bf16 per X smem row (32 + 8 pad)
#define NTILES ((N_NODES + 127) / 128)

__global__ __launch_bounds__(256) void gemm_score_kernel(
    const float* __restrict__ x, const float* __restrict__ W,
    const float* __restrict__ b, const float* __restrict__ a_w, int N)
{
    extern __shared__ char smem[];
    __nv_bfloat16* Whi = (__nv_bfloat16*)smem;                       // [128][WROW]
    __nv_bfloat16* Wlo = (__nv_bfloat16*)(smem + 34816);
    __nv_bfloat16* Xhi = (__nv_bfloat16*)(smem + 69632);             // [128][XROW]
    __nv_bfloat16* Xlo = (__nv_bfloat16*)(smem + 79872);
    float* sPartD = (float*)(smem + 90112);                          // [2][128]
    float* sPartS = (float*)(smem + 91136);                          // [2][128]

    const int tid  = threadIdx.x;
    const int wid  = tid >> 5;
    const int lane = tid & 31;

    const int warpM = (wid >> 1) * 32;
    const int warpN = (wid & 1) * 64;

    // ---- once per block: convert W (fp32 [k][n]) -> smem bf16 hi/lo ----
    #pragma unroll
    for (int it = 0; it < 8; ++it) {
        int idx8 = tid + it * 256;
        int k   = idx8 >> 4;
        int n8  = (idx8 & 15) * 8;
        const float4* wp = (const float4*)(W + (size_t)k * 128 + n8);
        float4 f0 = wp[0], f1 = wp[1];
        float vf[8] = {f0.x, f0.y, f0.z, f0.w, f1.x, f1.y, f1.z, f1.w};
        unsigned hiw[4], low[4];
        #pragma unroll
        for (int p = 0; p < 4; ++p) {
            float va = vf[p * 2], vb = vf[p * 2 + 1];
            __nv_bfloat16 ha = __float2bfloat16_rn(va);
            __nv_bfloat16 hb = __float2bfloat16_rn(vb);
            hiw[p] = pack_bf2(__bfloat162float(ha), __bfloat162float(hb));
            low[p] = pack_bf2(va - __bfloat162float(ha), vb - __bfloat162float(hb));
        }
        *(uint4*)(Whi + (size_t)k * WROW + n8) = *(uint4*)hiw;
        *(uint4*)(Wlo + (size_t)k * WROW + n8) = *(uint4*)low;
    }

    // per-thread constant maps
    const int lx_row = tid >> 1;
    const int lx_kb  = (tid & 1) * 16;
    const unsigned a_off = (unsigned)((warpM + (lane & 15)) * XROW + (lane >> 4) * 8);
    const unsigned aHi_base = sptr(Xhi) + a_off * 2;
    const unsigned aLo_base = sptr(Xlo) + a_off * 2;
    const int g   = lane >> 2;
    const int tig = lane & 3;

    for (int tile = blockIdx.x; tile < NTILES; tile += gridDim.x) {
        const int rowBase = tile * 128;
        const int grow_l  = rowBase + lx_row;

        float c[2][8][4];
        #pragma unroll
        for (int mf = 0; mf < 2; ++mf)
            #pragma unroll
            for (int nf = 0; nf < 8; ++nf)
                #pragma unroll
                for (int r = 0; r < 4; ++r) c[mf][nf][r] = 0.f;

        float4 fx[4];
        {   // prefetch k-subtile 0
            const float* xp = x + (size_t)grow_l * 128 + lx_kb;
            if (grow_l < N) {
                fx[0] = *(const float4*)(xp);      fx[1] = *(const float4*)(xp + 4);
                fx[2] = *(const float4*)(xp + 8);  fx[3] = *(const float4*)(xp + 12);
            } else {
                fx[0] = fx[1] = fx[2] = fx[3] = make_float4(0.f, 0.f, 0.f, 0.f);
            }
        }

        for (int t = 0; t < 4; ++t) {
            __syncthreads();   // X buffer free (and W ready on first pass)
            {
                float vf[16] = {fx[0].x, fx[0].y, fx[0].z, fx[0].w,
                                fx[1].x, fx[1].y, fx[1].z, fx[1].w,
                                fx[2].x, fx[2].y, fx[2].z, fx[2].w,
                                fx[3].x, fx[3].y, fx[3].z, fx[3].w};
                __nv_bfloat16* xh = Xhi + (size_t)lx_row * XROW + lx_kb;
                __nv_bfloat16* xl = Xlo + (size_t)lx_row * XROW + lx_kb;
                #pragma unroll
                for (int p = 0; p < 8; ++p) {
                    float va = vf[p * 2], vb = vf[p * 2 + 1];
                    __nv_bfloat16 ha = __float2bfloat16_rn(va);
                    __nv_bfloat16 hb = __float2bfloat16_rn(vb);
                    *(unsigned*)(xh + p * 2) = pack_bf2(__bfloat162float(ha), __bfloat162float(hb));
                    *(unsigned*)(xl + p * 2) = pack_bf2(va - __bfloat162float(ha),
                                                        vb - __bfloat162float(hb));
                }
            }
            __syncthreads();

            if (t < 3 && grow_l < N) {   // prefetch next subtile under HMMA
                const float* xp = x + (size_t)grow_l * 128 + (t + 1) * 32 + lx_kb;
                fx[0] = *(const float4*)(xp);      fx[1] = *(const float4*)(xp + 4);
                fx[2] = *(const float4*)(xp + 8);  fx[3] = *(const float4*)(xp + 12);
            }

            #pragma unroll
            for (int kk = 0; kk < 32; kk += 16) {
                unsigned Ah[2][4], Al[2][4];
                #pragma unroll
                for (int mf = 0; mf < 2; ++mf) {
                    unsigned off = (unsigned)(mf * 16 * XROW + kk) * 2;
                    ldsm_x4(aHi_base + off, Ah[mf][0], Ah[mf][1], Ah[mf][2], Ah[mf][3]);
                    ldsm_x4(aLo_base + off, Al[mf][0], Al[mf][1], Al[mf][2], Al[mf][3]);
                }
                int kabs = t * 32 + kk;
                #pragma unroll
                for (int nf = 0; nf < 8; ++nf) {
                    int n = warpN + nf * 8;
                    unsigned boff = (unsigned)((kabs + (lane & 15)) * WROW + n) * 2;
                    unsigned bh0, bh1, bl0, bl1;
                    ldsm_x2t(sptr(Whi) + boff, bh0, bh1);
                    ldsm_x2t(sptr(Wlo) + boff, bl0, bl1);
                    #pragma unroll
                    for (int mf = 0; mf < 2; ++mf) {
                        mma_bf16(c[mf][nf], Ah[mf][0], Ah[mf][1], Ah[mf][2], Ah[mf][3], bh0, bh1);
                        mma_bf16(c[mf][nf], Ah[mf][0], Ah[mf][1], Ah[mf][2], Ah[mf][3], bl0, bl1);
                        mma_bf16(c[mf][nf], Al[mf][0], Al[mf][1], Al[mf][2], Al[mf][3], bh0, bh1);
                    }
                }
            }
        }

        // ---- epilogue: bias, store h as fp16, fused scores ----
        #pragma unroll
        for (int mf = 0; mf < 2; ++mf) {
            #pragma unroll
            for (int half = 0; half < 2; ++half) {
                int lrow = warpM + mf * 16 + half * 8 + g;
                int grow = rowBase + lrow;
                float sd = 0.f, ss = 0.f;
                #pragma unroll
                for (int nf = 0; nf < 8; ++nf) {
                    int col = warpN + nf * 8 + tig * 2;
                    float o0 = c[mf][nf][half * 2 + 0] + __ldg(b + col);
                    float o1 = c[mf][nf][half * 2 + 1] + __ldg(b + col + 1);
                    if (grow < N) {
                        __half2 hh = __floats2half2_rn(o0, o1);
                        *(__half2*)(g_h16 + (size_t)grow * 128 + col) = hh;
                    }
                    sd += o0 * __ldg(a_w + col)       + o1 * __ldg(a_w + col + 1);
                    ss += o0 * __ldg(a_w + 128 + col) + o1 * __ldg(a_w + 129 + col);
                }
                #pragma unroll
                for (int o = 1; o <= 2; o <<= 1) {
                    sd += __shfl_xor_sync(0xFFFFFFFFu, sd, o);
                    ss += __shfl_xor_sync(0xFFFFFFFFu, ss, o);
                }
                if (tig == 0) {
                    sPartD[(wid & 1) * 128 + lrow] = sd;
                    sPartS[(wid & 1) * 128 + lrow] = ss;
                }
            }
        }
        __syncthreads();
        if (tid < 128) {
            int grow = rowBase + tid;
            if (grow < N) {
                g_sdst[grow] = sPartD[tid] + sPartD[128 + tid];
                g_ssrc[grow] = sPartS[tid] + sPartS[128 + tid];
            }
        }
        // next-iteration __syncthreads() protects sPart / X reuse
    }
}

// ---------------------------------------------------------------------------
// K2: row_ptr via lower_bound on sorted edge_dst
// ---------------------------------------------------------------------------
__global__ __launch_bounds__(256) void rowptr_kernel(const int* __restrict__ edge_dst,
                                                     int N, int E)
{
    int n = blockIdx.x * blockDim.x + threadIdx.x;
    if (n > N) return;
    int lo = 0, hi = E;
    while (lo < hi) {
        int mid = (lo + hi) >> 1;
        if (edge_dst[mid] < n) lo = mid + 1; else hi = mid;
    }
    g_rowptr[n] = lo;
}

// ---------------------------------------------------------------------------
// K3: warp-per-dst-node SINGLE-PASS segment softmax + aggregation.
//     fp16 h gather (half the L2 bytes); fp32 weights/accumulators.
// ---------------------------------------------------------------------------
__global__ __launch_bounds__(256) void agg_kernel(const int* __restrict__ edge_src,
                                                  const float* __restrict__ a_b,
                                                  float* __restrict__ out, int N)
{
    int warp = (blockIdx.x * blockDim.x + threadIdx.x) >> 5;
    int lane = threadIdx.x & 31;
    if (warp >= N) return;

    int s = g_rowptr[warp];
    int e = g_rowptr[warp + 1];
    float4* op = (float4*)(out + (size_t)warp * 128);

    if (s == e) { op[lane] = make_float4(0.f, 0.f, 0.f, 0.f); return; }

    float base = g_sdst[warp] + a_b[0];

    float sum = 0.f;
    unsigned long long accA01 = 0ull, accA23 = 0ull;
    unsigned long long accB01 = 0ull, accB23 = 0ull;

    for (int chunk = s; chunk < e; chunk += 32) {
        int i = chunk + lane;
        int src = 0;
        float w = 0.f;
        if (i < e) {
            src = edge_src[i];
            float l = base + g_ssrc[src];
            l = (l >= 0.f) ? l : 0.01f * l;
            w = __expf(l);
        }
        sum += w;
        int cnt = min(32, e - chunk);
        int j = 0;
        #pragma unroll 2
        for (; j + 2 <= cnt; j += 2) {
            float wj0 = __shfl_sync(0xFFFFFFFFu, w, j);
            int   sj0 = __shfl_sync(0xFFFFFFFFu, src, j);
            float wj1 = __shfl_sync(0xFFFFFFFFu, w, j + 1);
            int   sj1 = __shfl_sync(0xFFFFFFFFu, src, j + 1);
            uint2 v0 = ((const uint2*)(g_h16 + (size_t)sj0 * 128))[lane];
            uint2 v1 = ((const uint2*)(g_h16 + (size_t)sj1 * 128))[lane];
            float2 f001 = __half22float2(*(__half2*)&v0.x);
            float2 f023 = __half22float2(*(__half2*)&v0.y);
            float2 f101 = __half22float2(*(__half2*)&v1.x);
            float2 f123 = __half22float2(*(__half2*)&v1.y);
            unsigned long long w20 = pk2(wj0, wj0);
            unsigned long long w21 = pk2(wj1, wj1);
            ffma2(accA01, w20, pk2(f001.x, f001.y));
            ffma2(accA23, w20, pk2(f023.x, f023.y));
            ffma2(accB01, w21, pk2(f101.x, f101.y));
            ffma2(accB23, w21, pk2(f123.x, f123.y));
        }
        if (j < cnt) {
            float wj = __shfl_sync(0xFFFFFFFFu, w, j);
            int   sj = __shfl_sync(0xFFFFFFFFu, src, j);
            uint2 v = ((const uint2*)(g_h16 + (size_t)sj * 128))[lane];
            float2 f01 = __half22float2(*(__half2*)&v.x);
            float2 f23 = __half22float2(*(__half2*)&v.y);
            unsigned long long w2 = pk2(wj, wj);
            ffma2(accA01, w2, pk2(f01.x, f01.y));
            ffma2(accA23, w2, pk2(f23.x, f23.y));
        }
    }
    #pragma unroll
    for (int o = 16; o; o >>= 1)
        sum += __shfl_xor_sync(0xFFFFFFFFu, sum, o);

    float inv = 1.0f / fmaxf(sum, 1e-16f);

    float a0, a1, a2, a3, b0, b1, b2, b3;
    upk2(accA01, a0, a1); upk2(accA23, a2, a3);
    upk2(accB01, b0, b1); upk2(accB23, b2, b3);
    op[lane] = make_float4((a0 + b0) * inv, (a1 + b1) * inv,
                           (a2 + b2) * inv, (a3 + b3) * inv);
}

// ---------------------------------------------------------------------------
extern "C" void kernel_launch(void* const* d_in, const int* in_sizes, int n_in,
                              void* d_out, int out_size)
{
    const float* x        = (const float*)d_in[0];
    const int*   edge_src = (const int*)d_in[1];
    const int*   edge_dst = (const int*)d_in[2];
    const float* W        = (const float*)d_in[3];
    const float* b        = (const float*)d_in[4];
    const float* a_w      = (const float*)d_in[5];
    const float* a_b      = (const float*)d_in[6];
    float*       out      = (float*)d_out;

    const int N = in_sizes[0] / DOUT;   // 50000
    const int E = in_sizes[1];          // 800000

    const int SMEM_BYTES = 92160;
    cudaFuncSetAttribute(gemm_score_kernel,
                         cudaFuncAttributeMaxDynamicSharedMemorySize, SMEM_BYTES);

    gemm_score_kernel<<<148, 256, SMEM_BYTES>>>(x, W, b, a_w, N);
    rowptr_kernel<<<(N + 1 + 255) / 256, 256>>>(edge_dst, N, E);
    agg_kernel<<<(N + 7) / 8, 256>>>(edge_src, a_b, out, N);
}

// round 16
// speedup vs baseline: 1.5219x; 1.0705x over previous
#include <cuda_runtime.h>
#include <cuda_bf16.h>
#include <cuda_fp16.h>
#include <math_constants.h>

#define N_NODES 50000
#define N_EDGES 800000
#define DOUT 128

// scratch (device globals — no allocation allowed)
__device__ __half g_h16[(size_t)N_NODES * DOUT];   // 12.8 MB (L2-resident)
__device__ float g_sdst[N_NODES];
__device__ float g_ssrc[N_NODES];
__device__ int   g_rowptr[N_NODES + 1];

// ---------------------------------------------------------------------------
// helpers
// ---------------------------------------------------------------------------
__device__ __forceinline__ unsigned long long pk2(float lo, float hi) {
    unsigned long long r;
    asm("mov.b64 %0, {%1, %2};" : "=l"(r) : "f"(lo), "f"(hi));
    return r;
}
__device__ __forceinline__ void upk2(unsigned long long v, float& lo, float& hi) {
    asm("mov.b64 {%0, %1}, %2;" : "=f"(lo), "=f"(hi) : "l"(v));
}
__device__ __forceinline__ void ffma2(unsigned long long& d,
                                      unsigned long long a, unsigned long long b) {
    asm("fma.rn.f32x2 %0, %1, %2, %0;" : "+l"(d) : "l"(a), "l"(b));
}
__device__ __forceinline__ unsigned sptr(const void* p) {
    return (unsigned)__cvta_generic_to_shared(p);
}
__device__ __forceinline__ unsigned pack_bf2(float a, float b) {
    __nv_bfloat162 t = __floats2bfloat162_rn(a, b);
    return *(unsigned*)&t;
}
__device__ __forceinline__ void ldsm_x4(unsigned addr, unsigned& r0, unsigned& r1,
                                        unsigned& r2, unsigned& r3) {
    asm volatile("ldmatrix.sync.aligned.m8n8.x4.shared.b16 {%0,%1,%2,%3}, [%4];"
                 : "=r"(r0), "=r"(r1), "=r"(r2), "=r"(r3) : "r"(addr));
}
__device__ __forceinline__ void ldsm_x2t(unsigned addr, unsigned& r0, unsigned& r1) {
    asm volatile("ldmatrix.sync.aligned.m8n8.x2.trans.shared.b16 {%0,%1}, [%2];"
                 : "=r"(r0), "=r"(r1) : "r"(addr));
}
__device__ __forceinline__ void mma_bf16(float* c, unsigned a0, unsigned a1,
                                         unsigned a2, unsigned a3,
                                         unsigned b0, unsigned b1) {
    asm volatile(
        "mma.sync.aligned.m16n8k16.row.col.f32.bf16.bf16.f32 "
        "{%0,%1,%2,%3}, {%4,%5,%6,%7}, {%8,%9}, {%0,%1,%2,%3};\n"
        : "+f"(c[0]), "+f"(c[1]), "+f"(c[2]), "+f"(c[3])
        : "r"(a0), "r"(a1), "r"(a2), "r"(a3), "r"(b0), "r"(b1));
}

// ---------------------------------------------------------------------------
// K1: PERSISTENT fused GEMM + scores. bf16x2 (3-term) tensor-core GEMM.
//     512 threads (16 warps, 4M x 4N, 32x32 warp tiles), 128x128 block tile.
//     Double-buffered X stages; 1 sync per k-subtile; cross-tile prefetch.
// ---------------------------------------------------------------------------
#define WROW 136   // bf16 per W smem row (128 + 8 pad)
#define XROW 40    // bf16 per X smem row (32 + 8 pad)
#define NTILES ((N_NODES + 127) / 128)
#define XSTAGE (128 * XROW)          // bf16 elems per stage (10240 B)

__global__ __launch_bounds__(512) void gemm_score_kernel(
    const float* __restrict__ x, const float* __restrict__ W,
    const float* __restrict__ b, const float* __restrict__ a_w, int N)
{
    extern __shared__ char smem[];
    __nv_bfloat16* Whi = (__nv_bfloat16*)smem;                 // [128][WROW]
    __nv_bfloat16* Wlo = (__nv_bfloat16*)(smem + 34816);
    __nv_bfloat16* Xhi = (__nv_bfloat16*)(smem + 69632);       // [2][128][XROW]
    __nv_bfloat16* Xlo = (__nv_bfloat16*)(smem + 90112);       // [2][128][XROW]
    float* sPartD = (float*)(smem + 110592);                   // [4][128]
    float* sPartS = (float*)(smem + 112640);                   // [4][128]

    const int tid  = threadIdx.x;
    const int wid  = tid >> 5;
    const int lane = tid & 31;

    const int warpM = (wid >> 2) * 32;
    const int warpN = (wid & 3) * 32;

    // ---- once per block: convert W (fp32 [k][n]) -> smem bf16 hi/lo ----
    #pragma unroll
    for (int it = 0; it < 4; ++it) {
        int idx8 = tid + it * 512;           // 0..2047
        int k   = idx8 >> 4;
        int n8  = (idx8 & 15) * 8;
        const float4* wp = (const float4*)(W + (size_t)k * 128 + n8);
        float4 f0 = wp[0], f1 = wp[1];
        float vf[8] = {f0.x, f0.y, f0.z, f0.w, f1.x, f1.y, f1.z, f1.w};
        unsigned hiw[4], low[4];
        #pragma unroll
        for (int p = 0; p < 4; ++p) {
            float va = vf[p * 2], vb = vf[p * 2 + 1];
            __nv_bfloat16 ha = __float2bfloat16_rn(va);
            __nv_bfloat16 hb = __float2bfloat16_rn(vb);
            hiw[p] = pack_bf2(__bfloat162float(ha), __bfloat162float(hb));
            low[p] = pack_bf2(va - __bfloat162float(ha), vb - __bfloat162float(hb));
        }
        *(uint4*)(Whi + (size_t)k * WROW + n8) = *(uint4*)hiw;
        *(uint4*)(Wlo + (size_t)k * WROW + n8) = *(uint4*)low;
    }

    // per-thread constant maps
    const int lx_row = tid >> 2;              // 0..127
    const int lx_kb  = (tid & 3) * 8;         // 0,8,16,24
    const unsigned a_off = (unsigned)((warpM + (lane & 15)) * XROW + (lane >> 4) * 8) * 2;
    const unsigned xhi_s = sptr(Xhi);
    const unsigned xlo_s = sptr(Xlo);
    const int g   = lane >> 2;
    const int tig = lane & 3;

    const int tile0 = blockIdx.x;

    float4 fx[2];
    {   // prefetch (tile0, subtile 0)
        int grow = tile0 * 128 + lx_row;
        if (grow < N) {
            const float* xp = x + (size_t)grow * 128 + lx_kb;
            fx[0] = *(const float4*)xp;
            fx[1] = *(const float4*)(xp + 4);
        } else {
            fx[0] = fx[1] = make_float4(0.f, 0.f, 0.f, 0.f);
        }
    }

    for (int tile = tile0; tile < NTILES; tile += gridDim.x) {
        const int rowBase = tile * 128;

        float c[2][4][4];
        #pragma unroll
        for (int mf = 0; mf < 2; ++mf)
            #pragma unroll
            for (int nf = 0; nf < 4; ++nf)
                #pragma unroll
                for (int r = 0; r < 4; ++r) c[mf][nf][r] = 0.f;

        #pragma unroll
        for (int t = 0; t < 4; ++t) {
            const int stage = t & 1;
            // ---- STS current subtile into its stage ----
            {
                float vf[8] = {fx[0].x, fx[0].y, fx[0].z, fx[0].w,
                               fx[1].x, fx[1].y, fx[1].z, fx[1].w};
                unsigned hiw[4], low[4];
                #pragma unroll
                for (int p = 0; p < 4; ++p) {
                    float va = vf[p * 2], vb = vf[p * 2 + 1];
                    __nv_bfloat16 ha = __float2bfloat16_rn(va);
                    __nv_bfloat16 hb = __float2bfloat16_rn(vb);
                    hiw[p] = pack_bf2(__bfloat162float(ha), __bfloat162float(hb));
                    low[p] = pack_bf2(va - __bfloat162float(ha), vb - __bfloat162float(hb));
                }
                size_t off = (size_t)stage * XSTAGE + (size_t)lx_row * XROW + lx_kb;
                *(uint4*)(Xhi + off) = *(uint4*)hiw;
                *(uint4*)(Xlo + off) = *(uint4*)low;
            }
            __syncthreads();

            // ---- prefetch next subtile (next tile's subtile 0 at t==3) ----
            if (t < 3) {
                int grow = rowBase + lx_row;
                if (grow < N) {
                    const float* xp = x + (size_t)grow * 128 + (t + 1) * 32 + lx_kb;
                    fx[0] = *(const float4*)xp;
                    fx[1] = *(const float4*)(xp + 4);
                } else {
                    fx[0] = fx[1] = make_float4(0.f, 0.f, 0.f, 0.f);
                }
            } else {
                int ntile = tile + gridDim.x;
                if (ntile < NTILES) {
                    int grow = ntile * 128 + lx_row;
                    if (grow < N) {
                        const float* xp = x + (size_t)grow * 128 + lx_kb;
                        fx[0] = *(const float4*)xp;
                        fx[1] = *(const float4*)(xp + 4);
                    } else {
                        fx[0] = fx[1] = make_float4(0.f, 0.f, 0.f, 0.f);
                    }
                }
            }

            // ---- compute this subtile (2 k16 steps) ----
            const unsigned aHi_base = xhi_s + stage * (XSTAGE * 2) + a_off;
            const unsigned aLo_base = xlo_s + stage * (XSTAGE * 2) + a_off;
            #pragma unroll
            for (int kk = 0; kk < 32; kk += 16) {
                unsigned Ah[2][4], Al[2][4];
                #pragma unroll
                for (int mf = 0; mf < 2; ++mf) {
                    unsigned off = (unsigned)(mf * 16 * XROW + kk) * 2;
                    ldsm_x4(aHi_base + off, Ah[mf][0], Ah[mf][1], Ah[mf][2], Ah[mf][3]);
                    ldsm_x4(aLo_base + off, Al[mf][0], Al[mf][1], Al[mf][2], Al[mf][3]);
                }
                int kabs = t * 32 + kk;
                #pragma unroll
                for (int nf = 0; nf < 4; ++nf) {
                    int n = warpN + nf * 8;
                    unsigned boff = (unsigned)((kabs + (lane & 15)) * WROW + n) * 2;
                    unsigned bh0, bh1, bl0, bl1;
                    ldsm_x2t(sptr(Whi) + boff, bh0, bh1);
                    ldsm_x2t(sptr(Wlo) + boff, bl0, bl1);
                    #pragma unroll
                    for (int mf = 0; mf < 2; ++mf) {
                        mma_bf16(c[mf][nf], Ah[mf][0], Ah[mf][1], Ah[mf][2], Ah[mf][3], bh0, bh1);
                        mma_bf16(c[mf][nf], Ah[mf][0], Ah[mf][1], Ah[mf][2], Ah[mf][3], bl0, bl1);
                        mma_bf16(c[mf][nf], Al[mf][0], Al[mf][1], Al[mf][2], Al[mf][3], bh0, bh1);
                    }
                }
            }
        }

        // ---- epilogue: bias, store h as fp16, fused scores ----
        #pragma unroll
        for (int mf = 0; mf < 2; ++mf) {
            #pragma unroll
            for (int half = 0; half < 2; ++half) {
                int lrow = warpM + mf * 16 + half * 8 + g;
                int grow = rowBase + lrow;
                float sd = 0.f, ss = 0.f;
                #pragma unroll
                for (int nf = 0; nf < 4; ++nf) {
                    int col = warpN + nf * 8 + tig * 2;
                    float o0 = c[mf][nf][half * 2 + 0] + __ldg(b + col);
                    float o1 = c[mf][nf][half * 2 + 1] + __ldg(b + col + 1);
                    if (grow < N) {
                        __half2 hh = __floats2half2_rn(o0, o1);
                        *(__half2*)(g_h16 + (size_t)grow * 128 + col) = hh;
                    }
                    sd += o0 * __ldg(a_w + col)       + o1 * __ldg(a_w + col + 1);
                    ss += o0 * __ldg(a_w + 128 + col) + o1 * __ldg(a_w + 129 + col);
                }
                #pragma unroll
                for (int o = 1; o <= 2; o <<= 1) {
                    sd += __shfl_xor_sync(0xFFFFFFFFu, sd, o);
                    ss += __shfl_xor_sync(0xFFFFFFFFu, ss, o);
                }
                if (tig == 0) {
                    sPartD[(wid & 3) * 128 + lrow] = sd;
                    sPartS[(wid & 3) * 128 + lrow] = ss;
                }
            }
        }
        __syncthreads();
        if (tid < 128) {
            int grow = rowBase + tid;
            if (grow < N) {
                g_sdst[grow] = sPartD[tid] + sPartD[128 + tid]
                             + sPartD[256 + tid] + sPartD[384 + tid];
                g_ssrc[grow] = sPartS[tid] + sPartS[128 + tid]
                             + sPartS[256 + tid] + sPartS[384 + tid];
            }
        }
        __syncthreads();   // sPart + X stage-0 safe for next tile
    }
}

// ---------------------------------------------------------------------------
// K2: row_ptr via lower_bound on sorted edge_dst
// ---------------------------------------------------------------------------
__global__ __launch_bounds__(256) void rowptr_kernel(const int* __restrict__ edge_dst,
                                                     int N, int E)
{
    int n = blockIdx.x * blockDim.x + threadIdx.x;
    if (n > N) return;
    int lo = 0, hi = E;
    while (lo < hi) {
        int mid = (lo + hi) >> 1;
        if (edge_dst[mid] < n) lo = mid + 1; else hi = mid;
    }
    g_rowptr[n] = lo;
}

// ---------------------------------------------------------------------------
// K3: warp-per-dst-node SINGLE-PASS segment softmax + aggregation.
//     fp16 h gather (half the L2 bytes); fp32 weights/accumulators.
// ---------------------------------------------------------------------------
__global__ __launch_bounds__(256) void agg_kernel(const int* __restrict__ edge_src,
                                                  const float* __restrict__ a_b,
                                                  float* __restrict__ out, int N)
{
    int warp = (blockIdx.x * blockDim.x + threadIdx.x) >> 5;
    int lane = threadIdx.x & 31;
    if (warp >= N) return;

    int s = g_rowptr[warp];
    int e = g_rowptr[warp + 1];
    float4* op = (float4*)(out + (size_t)warp * 128);

    if (s == e) { op[lane] = make_float4(0.f, 0.f, 0.f, 0.f); return; }

    float base = g_sdst[warp] + a_b[0];

    float sum = 0.f;
    unsigned long long accA01 = 0ull, accA23 = 0ull;
    unsigned long long accB01 = 0ull, accB23 = 0ull;

    for (int chunk = s; chunk < e; chunk += 32) {
        int i = chunk + lane;
        int src = 0;
        float w = 0.f;
        if (i < e) {
            src = edge_src[i];
            float l = base + g_ssrc[src];
            l = (l >= 0.f) ? l : 0.01f * l;
            w = __expf(l);
        }
        sum += w;
        int cnt = min(32, e - chunk);
        int j = 0;
        #pragma unroll 2
        for (; j + 2 <= cnt; j += 2) {
            float wj0 = __shfl_sync(0xFFFFFFFFu, w, j);
            int   sj0 = __shfl_sync(0xFFFFFFFFu, src, j);
            float wj1 = __shfl_sync(0xFFFFFFFFu, w, j + 1);
            int   sj1 = __shfl_sync(0xFFFFFFFFu, src, j + 1);
            uint2 v0 = ((const uint2*)(g_h16 + (size_t)sj0 * 128))[lane];
            uint2 v1 = ((const uint2*)(g_h16 + (size_t)sj1 * 128))[lane];
            float2 f001 = __half22float2(*(__half2*)&v0.x);
            float2 f023 = __half22float2(*(__half2*)&v0.y);
            float2 f101 = __half22float2(*(__half2*)&v1.x);
            float2 f123 = __half22float2(*(__half2*)&v1.y);
            unsigned long long w20 = pk2(wj0, wj0);
            unsigned long long w21 = pk2(wj1, wj1);
            ffma2(accA01, w20, pk2(f001.x, f001.y));
            ffma2(accA23, w20, pk2(f023.x, f023.y));
            ffma2(accB01, w21, pk2(f101.x, f101.y));
            ffma2(accB23, w21, pk2(f123.x, f123.y));
        }
        if (j < cnt) {
            float wj = __shfl_sync(0xFFFFFFFFu, w, j);
            int   sj = __shfl_sync(0xFFFFFFFFu, src, j);
            uint2 v = ((const uint2*)(g_h16 + (size_t)sj * 128))[lane];
            float2 f01 = __half22float2(*(__half2*)&v.x);
            float2 f23 = __half22float2(*(__half2*)&v.y);
            unsigned long long w2 = pk2(wj, wj);
            ffma2(accA01, w2, pk2(f01.x, f01.y));
            ffma2(accA23, w2, pk2(f23.x, f23.y));
        }
    }
    #pragma unroll
    for (int o = 16; o; o >>= 1)
        sum += __shfl_xor_sync(0xFFFFFFFFu, sum, o);

    float inv = 1.0f / fmaxf(sum, 1e-16f);

    float a0, a1, a2, a3, b0, b1, b2, b3;
    upk2(accA01, a0, a1); upk2(accA23, a2, a3);
    upk2(accB01, b0, b1); upk2(accB23, b2, b3);
    op[lane] = make_float4((a0 + b0) * inv, (a1 + b1) * inv,
                           (a2 + b2) * inv, (a3 + b3) * inv);
}

// ---------------------------------------------------------------------------
extern "C" void kernel_launch(void* const* d_in, const int* in_sizes, int n_in,
                              void* d_out, int out_size)
{
    const float* x        = (const float*)d_in[0];
    const int*   edge_src = (const int*)d_in[1];
    const int*   edge_dst = (const int*)d_in[2];
    const float* W        = (const float*)d_in[3];
    const float* b        = (const float*)d_in[4];
    const float* a_w      = (const float*)d_in[5];
    const float* a_b      = (const float*)d_in[6];
    float*       out      = (float*)d_out;

    const int N = in_sizes[0] / DOUT;   // 50000
    const int E = in_sizes[1];          // 800000

    const int SMEM_BYTES = 114688;
    cudaFuncSetAttribute(gemm_score_kernel,
                         cudaFuncAttributeMaxDynamicSharedMemorySize, SMEM_BYTES);

    gemm_score_kernel<<<148, 512, SMEM_BYTES>>>(x, W, b, a_w, N);
    rowptr_kernel<<<(N + 1 + 255) / 256, 256>>>(edge_dst, N, E);
    agg_kernel<<<(N + 7) / 8, 256>>>(edge_src, a_b, out, N);
}